// round 7
// baseline (speedup 1.0000x reference)
#include <cuda_runtime.h>
#include <cstdint>

// ---------------- problem constants ----------------
#define BATCH_N   1048576
#define IN_SZ     64
#define HID       16
#define KDIM      80          // IN_SZ + HID
#define NDIM      80          // 5 * HID
#define TILE_M    128
#define NTHREADS  256

// A smem: fragment-packed. Per 16-row tile: [kt=10][qr=8][qc=4][4 floats] = 1280 floats
#define A_TILE_FLOATS 1280
#define A_FLOATS (8 * A_TILE_FLOATS)   // 10240
#define SMEM_FLOATS (A_FLOATS + NDIM)
#define SMEM_BYTES  (SMEM_FLOATS * 4)  // 41280

// B fragments: [kt=10][np=5][lane=32][4] = 6400 tf32 values
#define BFRAG_FLOATS 6400
__device__ uint32_t g_Bfrag[BFRAG_FLOATS];
__device__ float    g_bias[NDIM];

static __device__ __forceinline__ uint32_t f2tf32(float f) {
    uint32_t u;
    asm("cvt.rna.tf32.f32 %0, %1;" : "=r"(u) : "f"(f));
    return u;
}

static __device__ __forceinline__ void mma_tf32(float* c, const uint32_t* a,
                                                uint32_t b0, uint32_t b1) {
    asm volatile(
        "mma.sync.aligned.m16n8k8.row.col.f32.tf32.tf32.f32 "
        "{%0,%1,%2,%3}, {%4,%5,%6,%7}, {%8,%9}, {%0,%1,%2,%3};"
        : "+f"(c[0]), "+f"(c[1]), "+f"(c[2]), "+f"(c[3])
        : "r"(a[0]), "r"(a[1]), "r"(a[2]), "r"(a[3]), "r"(b0), "r"(b1));
}

static __device__ __forceinline__ float tanh_fast(float x) {
    float e = __expf(-2.0f * fabsf(x));
    float t = __fdividef(1.0f - e, 1.0f + e);
    return copysignf(t, x);
}
static __device__ __forceinline__ float softplus_fast(float x) {
    return fmaxf(x, 0.0f) + __logf(1.0f + __expf(-fabsf(x)));
}

// ---------------- prep: pack W into per-lane mma B-fragments + bias ----------------
// g_Bfrag index i = ((kt*5 + np)*32 + lane)*4 + slot
//   lane = qr*4 + qc ; nt = 2*np + (slot>>1) ; pos = slot&1
//   value = tf32( W[k = kt*8 + qc + 4*pos][n = nt*8 + qr] )   (W as [k][5*16])
__global__ void prep_kernel(
    const float* __restrict__ W_i, const float* __restrict__ b_i,
    const float* __restrict__ W_f, const float* __restrict__ b_f,
    const float* __restrict__ W_o, const float* __restrict__ b_o,
    const float* __restrict__ W_c, const float* __restrict__ b_c,
    const float* __restrict__ W_d, const float* __restrict__ b_d)
{
    int i = blockIdx.x * blockDim.x + threadIdx.x;
    if (i < BFRAG_FLOATS) {
        int slot = i & 3;
        int lane = (i >> 2) & 31;
        int rest = i >> 7;            // 0..49
        int np = rest % 5;
        int kt = rest / 5;
        int qr = lane >> 2;
        int qc = lane & 3;
        int nt = 2 * np + (slot >> 1);
        int pos = slot & 1;
        int k = kt * 8 + qc + 4 * pos;
        int n = nt * 8 + qr;
        int g = n >> 4, c = n & 15;
        const float* W = (g == 0) ? W_i : (g == 1) ? W_f : (g == 2) ? W_o
                       : (g == 3) ? W_c : W_d;
        g_Bfrag[i] = f2tf32(W[k * HID + c]);
    } else if (i < BFRAG_FLOATS + NDIM) {
        int n = i - BFRAG_FLOATS;
        int g = n >> 4, c = n & 15;
        const float* B = (g == 0) ? b_i : (g == 1) ? b_f : (g == 2) ? b_o
                       : (g == 3) ? b_c : b_d;
        g_bias[n] = B[c];
    }
}

__global__ void __launch_bounds__(NTHREADS, 4) ctlstm_kernel(
    const float* __restrict__ x,
    const float* __restrict__ h_prev,
    const float* __restrict__ c_prev,
    const float* __restrict__ delta_t,
    float* __restrict__ out_h, float* __restrict__ out_c)
{
    extern __shared__ uint32_t smem[];
    uint32_t* As = smem;                                    // fragment-packed A
    float*    bs = reinterpret_cast<float*>(smem + A_FLOATS); // bias[80]

    const int tid  = threadIdx.x;
    const int warp = tid >> 5;
    const int lane = tid & 31;
    const int qr   = lane >> 2;   // 0..7
    const int qc   = lane & 3;    // 0..3
    const int row0 = blockIdx.x * TILE_M;

    // ---- bias copy ----
    if (tid < NDIM) bs[tid] = g_bias[tid];

    // ---- fill A into fragment-packed layout ----
    // item = (t*8 + qrf)*10 + kt ; each item loads 4 float4 (rows r, r+8; k-halves)
    // and writes 4 swizzled STS.128 fragment quads.
    #pragma unroll
    for (int it = 0; it < 3; it++) {
        int item = it * NTHREADS + tid;
        if (item < 640) {
            int kt  = item % 10;
            int g2  = item / 10;
            int qrf = g2 & 7;
            int t   = g2 >> 3;
            int r0g = row0 + t * 16 + qrf;
            const float* p0;
            const float* p1;
            if (kt < 8) {
                p0 = x + (size_t)r0g * IN_SZ + kt * 8;
                p1 = p0 + 8 * IN_SZ;
            } else {
                p0 = h_prev + (size_t)r0g * HID + (kt - 8) * 8;
                p1 = p0 + 8 * HID;
            }
            float4 f0a = *reinterpret_cast<const float4*>(p0);
            float4 f0b = *reinterpret_cast<const float4*>(p0 + 4);
            float4 f1a = *reinterpret_cast<const float4*>(p1);
            float4 f1b = *reinterpret_cast<const float4*>(p1 + 4);
            float a0[4] = {f0a.x, f0a.y, f0a.z, f0a.w};   // (r,   k..k+3)
            float a1[4] = {f1a.x, f1a.y, f1a.z, f1a.w};   // (r+8, k..k+3)
            float a2[4] = {f0b.x, f0b.y, f0b.z, f0b.w};   // (r,   k+4..k+7)
            float a3[4] = {f1b.x, f1b.y, f1b.z, f1b.w};   // (r+8, k+4..k+7)
            uint32_t* dstbase = As + t * A_TILE_FLOATS + kt * 128 + qrf * 16;
            #pragma unroll
            for (int q = 0; q < 4; q++) {
                int phys = (q + qrf + kt) & 3;
                uint4 v;
                v.x = f2tf32(a0[q]);
                v.y = f2tf32(a1[q]);
                v.z = f2tf32(a2[q]);
                v.w = f2tf32(a3[q]);
                *reinterpret_cast<uint4*>(dstbase + phys * 4) = v;
            }
        }
    }
    __syncthreads();

    // ---- GEMM: per warp 16 rows x 80 cols; per kt: 1 LDS.128 (A) + 5 LDG.128 (B) ----
    float acc[10][4];
    #pragma unroll
    for (int nt = 0; nt < 10; nt++)
        #pragma unroll
        for (int c = 0; c < 4; c++) acc[nt][c] = 0.0f;

    const uint32_t* Aw = As + warp * A_TILE_FLOATS + qr * 16;
    const uint4* Bp = reinterpret_cast<const uint4*>(g_Bfrag) + lane;

    #pragma unroll
    for (int kt = 0; kt < 10; kt++) {
        uint4 av = *reinterpret_cast<const uint4*>(Aw + kt * 128 + (((qc + qr + kt) & 3) << 2));
        uint32_t a[4] = {av.x, av.y, av.z, av.w};
        #pragma unroll
        for (int np = 0; np < 5; np++) {
            uint4 bv = Bp[(kt * 5 + np) * 32];
            mma_tf32(acc[2 * np],     a, bv.x, bv.y);
            mma_tf32(acc[2 * np + 1], a, bv.z, bv.w);
        }
    }

    // ---- epilogue operands (loaded after MMA to keep loop reg pressure low) ----
    const int mbase = warp * 16;
    float2 cpv[2][2];
    float  dtv[2];
    #pragma unroll
    for (int rs = 0; rs < 2; rs++) {
        size_t row = (size_t)row0 + mbase + rs * 8 + qr;
        dtv[rs] = delta_t[row];
        #pragma unroll
        for (int jh = 0; jh < 2; jh++) {
            int j0 = jh * 8 + 2 * qc;
            cpv[rs][jh] = *reinterpret_cast<const float2*>(c_prev + row * HID + j0);
        }
    }

    // ---- epilogue: z col C = g*16 + jh*8 + 2*qc + b  <- acc[2*g + jh][rs*2 + b] ----
    #pragma unroll
    for (int rs = 0; rs < 2; rs++) {
        size_t row = (size_t)row0 + mbase + rs * 8 + qr;
        float dt = dtv[rs];
        #pragma unroll
        for (int jh = 0; jh < 2; jh++) {
            float2 cp = cpv[rs][jh];
            float cpin[2] = {cp.x, cp.y};
            float h2[2], c2[2];
            #pragma unroll
            for (int b = 0; b < 2; b++) {
                int C = jh * 8 + 2 * qc + b;
                float zi = acc[0 + jh][rs * 2 + b] + bs[C];
                float zf = acc[2 + jh][rs * 2 + b] + bs[16 + C];
                float zo = acc[4 + jh][rs * 2 + b] + bs[32 + C];
                float zc = acc[6 + jh][rs * 2 + b] + bs[48 + C];
                float zd = acc[8 + jh][rs * 2 + b] + bs[64 + C];
                float ig = tanh_fast(zi);
                float fg = tanh_fast(zf);
                float og = tanh_fast(zo);
                float ct = tanh_fast(zc);
                float decay = softplus_fast(zd);
                float cdec = cpin[b] * __expf(-decay * dt);
                float cn = fg * cdec + ig * ct;
                c2[b] = cn;
                h2[b] = og * tanh_fast(cn);
            }
            int j0 = jh * 8 + 2 * qc;
            *reinterpret_cast<float2*>(out_h + row * HID + j0) = make_float2(h2[0], h2[1]);
            *reinterpret_cast<float2*>(out_c + row * HID + j0) = make_float2(c2[0], c2[1]);
        }
    }
}

extern "C" void kernel_launch(void* const* d_in, const int* in_sizes, int n_in,
                              void* d_out, int out_size) {
    const float* x      = (const float*)d_in[0];
    const float* h_prev = (const float*)d_in[1];
    const float* c_prev = (const float*)d_in[2];
    const float* dt     = (const float*)d_in[3];
    const float* W_i = (const float*)d_in[4];
    const float* b_i = (const float*)d_in[5];
    const float* W_f = (const float*)d_in[6];
    const float* b_f = (const float*)d_in[7];
    const float* W_o = (const float*)d_in[8];
    const float* b_o = (const float*)d_in[9];
    const float* W_c = (const float*)d_in[10];
    const float* b_c = (const float*)d_in[11];
    const float* W_d = (const float*)d_in[12];
    const float* b_d = (const float*)d_in[13];

    float* out_h = (float*)d_out;
    float* out_c = out_h + (size_t)out_size / 2;  // (h_next, c_next) concatenated

    cudaFuncSetAttribute(ctlstm_kernel, cudaFuncAttributeMaxDynamicSharedMemorySize, SMEM_BYTES);

    // one-time weight fragment packing (graph-capturable, ordered before main)
    prep_kernel<<<(BFRAG_FLOATS + NDIM + 255) / 256, 256>>>(
        W_i, b_i, W_f, b_f, W_o, b_o, W_c, b_c, W_d, b_d);

    dim3 grid(BATCH_N / TILE_M);
    ctlstm_kernel<<<grid, NTHREADS, SMEM_BYTES>>>(
        x, h_prev, c_prev, dt, out_h, out_c);
}